// round 9
// baseline (speedup 1.0000x reference)
#include <cuda_runtime.h>
#include <cuda_fp16.h>
#include <cstdint>
#include <math.h>

#define PW 49
#define DD 128

// ---------------- smem layout (halfs) ----------------
// wq  [128][392] : resident Wqkv fp16
// wm  [128][136] : resident Wmerge fp16
// buf[g] (g=0,1): packed window buffer, pitch 136:
//    Q rows 0..55   (buffer rows 0..55)    q / attn-out
//    K rows 0..55   (buffer rows 56..111)
//    V rows 0..63   (buffer rows 112..175) v / x staging
//  Q A-frag reads of rows 56..63 alias into K rows 0..7 (finite garbage,
//  results discarded). Pad rows (Q/K 49..55, V 49..63) zeroed once, stores
//  guarded row<49 so they stay zero.
static constexpr int WQ_P = 392;
static constexpr int WM_P = 136;
static constexpr int BP   = 136;
static constexpr int WQ_OFF  = 0;
static constexpr int WM_OFF  = 128 * WQ_P;             // 50176
static constexpr int BUF_OFF = WM_OFF + 128 * WM_P;    // 67584
static constexpr int K_ROFF  = 56 * BP;
static constexpr int V_ROFF  = 112 * BP;
static constexpr int BUF_SZ  = 176 * BP;               // 23936
static constexpr int HALFS   = BUF_OFF + 2 * BUF_SZ;   // 115456
static constexpr int SMEM_BYTES = HALFS * 2;           // 230912

__device__ __forceinline__ uint32_t cvta_s(const void* p)
{
    return (uint32_t)__cvta_generic_to_shared(p);
}
__device__ __forceinline__ uint32_t f2h2(float a, float b)
{
    __half2 h = __floats2half2_rn(a, b);
    return *reinterpret_cast<uint32_t*>(&h);
}
__device__ __forceinline__ void gbar(int id)
{
    asm volatile("bar.sync %0, %1;" :: "r"(id), "r"(256) : "memory");
}

#define LDSM4(R0,R1,R2,R3,ADDR) \
    asm volatile("ldmatrix.sync.aligned.m8n8.x4.shared.b16 {%0,%1,%2,%3},[%4];" \
        : "=r"(R0),"=r"(R1),"=r"(R2),"=r"(R3) : "r"(ADDR))
#define LDSM4T(R0,R1,R2,R3,ADDR) \
    asm volatile("ldmatrix.sync.aligned.m8n8.x4.trans.shared.b16 {%0,%1,%2,%3},[%4];" \
        : "=r"(R0),"=r"(R1),"=r"(R2),"=r"(R3) : "r"(ADDR))
#define MMA(C0,C1,C2,C3,A0,A1,A2,A3,B0,B1) \
    asm volatile("mma.sync.aligned.m16n8k16.row.col.f32.f16.f16.f32 " \
        "{%0,%1,%2,%3},{%4,%5,%6,%7},{%8,%9},{%0,%1,%2,%3};" \
        : "+f"(C0),"+f"(C1),"+f"(C2),"+f"(C3) \
        : "r"(A0),"r"(A1),"r"(A2),"r"(A3),"r"(B0),"r"(B1))

__global__ void __launch_bounds__(512, 1)
rpmha_dual_kernel(const float* __restrict__ x,
                  const float* __restrict__ Wqkv,
                  const float* __restrict__ bqkv,
                  const float* __restrict__ Wmerge,
                  const float* __restrict__ bmerge,
                  const float* __restrict__ table,
                  float* __restrict__ out, int nwin)
{
    extern __shared__ __half sh[];
    __half* wq = sh + WQ_OFF;
    __half* wm = sh + WM_OFF;

    const int tid = threadIdx.x, warp = tid >> 5, lane = tid & 31;
    const int g    = warp >> 3;        // window group 0/1
    const int lw   = warp & 7;         // warp id within group
    const int gtid = tid & 255;        // thread id within group
    const int bid  = g + 1;            // named barrier id

    __half* bufQ = sh + BUF_OFF + g * BUF_SZ;
    __half* bufK = bufQ + K_ROFF;
    __half* bufV = bufQ + V_ROFF;
    const uint32_t q_s  = cvta_s(bufQ);
    const uint32_t k_s  = cvta_s(bufK);
    const uint32_t v_s  = cvta_s(bufV);
    const uint32_t wq_s = cvta_s(wq);
    const uint32_t wm_s = cvta_s(wm);
    const float scale = 0.17677669529663687f;  // 1/sqrt(32)

    // GEMM warp split within group: 2 (M) x 4 (N)
    const int wrow = (lw & 1) << 5;          // 0 / 32
    const int wq0  = (lw >> 1) * 96;         // phase-1 col base
    const int wc   = (lw >> 1) << 5;         // phase-3 col base
    // attention: 2 warps per head
    const int ah = lw & 3, amh = lw >> 2;

    // ---- one-time init: zero both buffers, load weights fp16 ----
    {
        uint2* bz = reinterpret_cast<uint2*>(sh + BUF_OFF);
        for (int i = tid; i < 2 * BUF_SZ / 4; i += 512) bz[i] = make_uint2(0u, 0u);
        for (int i = tid; i < 128 * 384; i += 512) {
            int r = i / 384, c = i - r * 384;
            wq[r * WQ_P + c] = __float2half_rn(Wqkv[i]);
        }
        for (int i = tid; i < 128 * 128; i += 512) {
            int r = i >> 7, c = i & 127;
            wm[r * WM_P + c] = __float2half_rn(Wmerge[i]);
        }
    }
    __syncthreads();

    const int stride = 2 * gridDim.x;
    int win = blockIdx.x * 2 + g;

    // x loader: fp32 global -> fp16 V-buffer rows 0..48
    auto load_x = [&](int w) {
        const float* src = x + (size_t)w * (PW * DD);
        #pragma unroll
        for (int t = 0; t < 7; t++) {
            int idx = gtid + t * 256;
            if (idx < PW * 32) {
                int row = idx >> 5, c4 = (idx & 31) << 2;
                float4 f = __ldg(reinterpret_cast<const float4*>(src + row * DD + c4));
                uint2 st; st.x = f2h2(f.x, f.y); st.y = f2h2(f.z, f.w);
                *reinterpret_cast<uint2*>(bufV + row * BP + c4) = st;
            }
        }
    };

    if (win < nwin) load_x(win);

    for (; win < nwin; win += stride) {
        gbar(bid);                         // (1) x ready; prev iter consumers done

        // ---- A fragments: x rows wrow..wrow+31 from V buffer ----
        uint32_t af[2][8][4];
        #pragma unroll
        for (int mt = 0; mt < 2; mt++) {
            uint32_t a0 = v_s + (((wrow + mt * 16) + (lane & 15)) * BP
                                 + ((lane >> 4) << 3)) * 2;
            #pragma unroll
            for (int kk = 0; kk < 8; kk++)
                LDSM4(af[mt][kk][0], af[mt][kk][1], af[mt][kk][2], af[mt][kk][3],
                      a0 + kk * 32);
        }
        gbar(bid);                         // (2) A-frags in regs; V writable

        // ================= Phase 1: qkv = x @ Wqkv + bqkv =================
        #pragma unroll
        for (int p = 0; p < 6; p++) {
            const int c0 = wq0 + p * 16;
            float acc[2][2][4];
            #pragma unroll
            for (int nt = 0; nt < 2; nt++) {
                int col = c0 + nt * 8 + ((lane & 3) << 1);
                float b0 = __ldg(bqkv + col), b1 = __ldg(bqkv + col + 1);
                #pragma unroll
                for (int mt = 0; mt < 2; mt++) {
                    acc[mt][nt][0] = b0; acc[mt][nt][1] = b1;
                    acc[mt][nt][2] = b0; acc[mt][nt][3] = b1;
                }
            }
            uint32_t wb0 = wq_s + ((lane & 15) * WQ_P + c0 + ((lane >> 4) << 3)) * 2;
            #pragma unroll
            for (int kk = 0; kk < 8; kk++) {
                uint32_t b[4];
                LDSM4T(b[0], b[1], b[2], b[3], wb0 + (kk * 16 * WQ_P) * 2);
                #pragma unroll
                for (int mt = 0; mt < 2; mt++) {
                    MMA(acc[mt][0][0],acc[mt][0][1],acc[mt][0][2],acc[mt][0][3],
                        af[mt][kk][0],af[mt][kk][1],af[mt][kk][2],af[mt][kk][3],
                        b[0], b[1]);
                    MMA(acc[mt][1][0],acc[mt][1][1],acc[mt][1][2],acc[mt][1][3],
                        af[mt][kk][0],af[mt][kk][1],af[mt][kk][2],af[mt][kk][3],
                        b[2], b[3]);
                }
            }
            const float mul = (c0 < 128) ? scale : 1.0f;
            __half* dstb = (c0 < 128) ? (bufQ + c0)
                        : (c0 < 256) ? (bufK + c0 - 128)
                                     : (bufV + c0 - 256);
            #pragma unroll
            for (int mt = 0; mt < 2; mt++) {
                const int r0 = wrow + mt * 16 + (lane >> 2);
                #pragma unroll
                for (int nt = 0; nt < 2; nt++) {
                    int cl = nt * 8 + ((lane & 3) << 1);
                    if (r0 < PW)
                        *reinterpret_cast<__half2*>(dstb + r0 * BP + cl) =
                            __floats2half2_rn(acc[mt][nt][0] * mul, acc[mt][nt][1] * mul);
                    if (r0 + 8 < PW)
                        *reinterpret_cast<__half2*>(dstb + (r0 + 8) * BP + cl) =
                            __floats2half2_rn(acc[mt][nt][2] * mul, acc[mt][nt][3] * mul);
                }
            }
        }
        gbar(bid);                         // (3) qkv ready

        // ============ Phase 2: attention (2 warps per head) ============
        {
            const int h = ah;
            uint32_t kb[7][4];
            #pragma unroll
            for (int nt = 0; nt < 7; nt++) {
                uint32_t addr = k_s + ((nt * 8 + (lane & 7)) * BP
                                       + h * 32 + ((lane >> 3) << 3)) * 2;
                LDSM4(kb[nt][0], kb[nt][1], kb[nt][2], kb[nt][3], addr);
            }

            #pragma unroll
            for (int mi = 0; mi < 2; mi++) {
                const int m = amh * 2 + mi;
                uint32_t qa[4], qa2[4];
                uint32_t qaddr = q_s + ((m * 16 + (lane & 15)) * BP
                                        + h * 32 + ((lane >> 4) << 3)) * 2;
                LDSM4(qa[0], qa[1], qa[2], qa[3], qaddr);
                LDSM4(qa2[0], qa2[1], qa2[2], qa2[3], qaddr + 32);

                float s[7][4];
                #pragma unroll
                for (int nt = 0; nt < 7; nt++) {
                    s[nt][0] = s[nt][1] = s[nt][2] = s[nt][3] = 0.f;
                    MMA(s[nt][0],s[nt][1],s[nt][2],s[nt][3],
                        qa[0],qa[1],qa[2],qa[3], kb[nt][0], kb[nt][1]);
                    MMA(s[nt][0],s[nt][1],s[nt][2],s[nt][3],
                        qa2[0],qa2[1],qa2[2],qa2[3], kb[nt][2], kb[nt][3]);
                }

                int i0 = m * 16 + (lane >> 2), i1 = i0 + 8;
                int i0c = (i0 < PW) ? i0 : 0, i1c = (i1 < PW) ? i1 : 0;
                int r0 = (i0c * 147) >> 10, c0i = i0c - r0 * 7;
                int r1 = (i1c * 147) >> 10, c1i = i1c - r1 * 7;
                #pragma unroll
                for (int nt = 0; nt < 7; nt++) {
                    #pragma unroll
                    for (int e = 0; e < 2; e++) {
                        int j = nt * 8 + ((lane & 3) << 1) + e;
                        if (j < PW) {
                            int rj = (j * 147) >> 10, cj = j - rj * 7;
                            s[nt][e]   += __ldg(table +
                                (((r0 - rj + 6) * 13) + (c0i - cj + 6)) * 4 + h);
                            s[nt][2+e] += __ldg(table +
                                (((r1 - rj + 6) * 13) + (c1i - cj + 6)) * 4 + h);
                        } else {
                            s[nt][e] = -1e30f; s[nt][2+e] = -1e30f;
                        }
                    }
                }

                float ml = -1e30f, mh2 = -1e30f;
                #pragma unroll
                for (int nt = 0; nt < 7; nt++) {
                    ml  = fmaxf(ml,  fmaxf(s[nt][0], s[nt][1]));
                    mh2 = fmaxf(mh2, fmaxf(s[nt][2], s[nt][3]));
                }
                ml  = fmaxf(ml,  __shfl_xor_sync(0xffffffffu, ml, 1));
                ml  = fmaxf(ml,  __shfl_xor_sync(0xffffffffu, ml, 2));
                mh2 = fmaxf(mh2, __shfl_xor_sync(0xffffffffu, mh2, 1));
                mh2 = fmaxf(mh2, __shfl_xor_sync(0xffffffffu, mh2, 2));
                float sl = 0.f, shs = 0.f;
                #pragma unroll
                for (int nt = 0; nt < 7; nt++) {
                    s[nt][0] = __expf(s[nt][0] - ml);  sl  += s[nt][0];
                    s[nt][1] = __expf(s[nt][1] - ml);  sl  += s[nt][1];
                    s[nt][2] = __expf(s[nt][2] - mh2); shs += s[nt][2];
                    s[nt][3] = __expf(s[nt][3] - mh2); shs += s[nt][3];
                }
                sl  += __shfl_xor_sync(0xffffffffu, sl, 1);
                sl  += __shfl_xor_sync(0xffffffffu, sl, 2);
                shs += __shfl_xor_sync(0xffffffffu, shs, 1);
                shs += __shfl_xor_sync(0xffffffffu, shs, 2);
                const float il = 1.f / sl, ih = 1.f / shs;

                uint32_t pa[4][4];
                #pragma unroll
                for (int kt = 0; kt < 4; kt++) {
                    int n0 = 2 * kt, n1 = 2 * kt + 1;
                    pa[kt][0] = f2h2(s[n0][0] * il, s[n0][1] * il);
                    pa[kt][1] = f2h2(s[n0][2] * ih, s[n0][3] * ih);
                    if (n1 < 7) {
                        pa[kt][2] = f2h2(s[n1][0] * il, s[n1][1] * il);
                        pa[kt][3] = f2h2(s[n1][2] * ih, s[n1][3] * ih);
                    } else { pa[kt][2] = 0u; pa[kt][3] = 0u; }
                }

                // V fragments loaded here (after s dead) to cap register peak
                float o[4][4];
                #pragma unroll
                for (int d = 0; d < 4; d++) o[d][0]=o[d][1]=o[d][2]=o[d][3]=0.f;
                #pragma unroll
                for (int kt = 0; kt < 4; kt++) {
                    uint32_t vb[8];
                    #pragma unroll
                    for (int dp = 0; dp < 2; dp++) {
                        uint32_t addr = v_s + ((kt * 16 + (lane & 15)) * BP
                                               + h * 32 + dp * 16 + ((lane >> 4) << 3)) * 2;
                        LDSM4T(vb[dp*4+0], vb[dp*4+1], vb[dp*4+2], vb[dp*4+3], addr);
                    }
                    MMA(o[0][0],o[0][1],o[0][2],o[0][3],
                        pa[kt][0],pa[kt][1],pa[kt][2],pa[kt][3], vb[0], vb[1]);
                    MMA(o[1][0],o[1][1],o[1][2],o[1][3],
                        pa[kt][0],pa[kt][1],pa[kt][2],pa[kt][3], vb[2], vb[3]);
                    MMA(o[2][0],o[2][1],o[2][2],o[2][3],
                        pa[kt][0],pa[kt][1],pa[kt][2],pa[kt][3], vb[4], vb[5]);
                    MMA(o[3][0],o[3][1],o[3][2],o[3][3],
                        pa[kt][0],pa[kt][1],pa[kt][2],pa[kt][3], vb[6], vb[7]);
                }
                const int orow = m * 16 + (lane >> 2);
                #pragma unroll
                for (int d = 0; d < 4; d++) {
                    int col = h * 32 + d * 8 + ((lane & 3) << 1);
                    if (orow < PW)
                        *reinterpret_cast<__half2*>(bufQ + orow * BP + col) =
                            __floats2half2_rn(o[d][0], o[d][1]);
                    if (orow + 8 < PW)
                        *reinterpret_cast<__half2*>(bufQ + (orow + 8) * BP + col) =
                            __floats2half2_rn(o[d][2], o[d][3]);
                }
            }
        }
        gbar(bid);                         // (4) attn-out ready; V free

        // prefetch next window's x into V (overlaps phase 3)
        if (win + stride < nwin) load_x(win + stride);

        // ============ Phase 3: out = attn_out @ Wmerge + bmerge ============
        {
            uint32_t af2[2][8][4];
            #pragma unroll
            for (int mt = 0; mt < 2; mt++) {
                uint32_t a0 = q_s + (((wrow + mt * 16) + (lane & 15)) * BP
                                     + ((lane >> 4) << 3)) * 2;
                #pragma unroll
                for (int kk = 0; kk < 8; kk++)
                    LDSM4(af2[mt][kk][0], af2[mt][kk][1], af2[mt][kk][2], af2[mt][kk][3],
                          a0 + kk * 32);
            }
            float* obase = out + (size_t)win * (PW * DD);

            #pragma unroll
            for (int nh = 0; nh < 2; nh++) {        // two 16-col halves
                const int c0 = wc + nh * 16;
                float acc[2][2][4];
                #pragma unroll
                for (int nt = 0; nt < 2; nt++) {
                    int col = c0 + nt * 8 + ((lane & 3) << 1);
                    float b0 = __ldg(bmerge + col), b1 = __ldg(bmerge + col + 1);
                    #pragma unroll
                    for (int mt = 0; mt < 2; mt++) {
                        acc[mt][nt][0] = b0; acc[mt][nt][1] = b1;
                        acc[mt][nt][2] = b0; acc[mt][nt][3] = b1;
                    }
                }
                uint32_t wm0 = wm_s + ((lane & 15) * WM_P + c0 + ((lane >> 4) << 3)) * 2;
                #pragma unroll
                for (int kk = 0; kk < 8; kk++) {
                    uint32_t b[4];
                    LDSM4T(b[0], b[1], b[2], b[3], wm0 + (kk * 16 * WM_P) * 2);
                    #pragma unroll
                    for (int mt = 0; mt < 2; mt++) {
                        MMA(acc[mt][0][0],acc[mt][0][1],acc[mt][0][2],acc[mt][0][3],
                            af2[mt][kk][0],af2[mt][kk][1],af2[mt][kk][2],af2[mt][kk][3],
                            b[0], b[1]);
                        MMA(acc[mt][1][0],acc[mt][1][1],acc[mt][1][2],acc[mt][1][3],
                            af2[mt][kk][0],af2[mt][kk][1],af2[mt][kk][2],af2[mt][kk][3],
                            b[2], b[3]);
                    }
                }
                #pragma unroll
                for (int mt = 0; mt < 2; mt++) {
                    const int r0 = wrow + mt * 16 + (lane >> 2);
                    #pragma unroll
                    for (int nt = 0; nt < 2; nt++) {
                        int col = c0 + nt * 8 + ((lane & 3) << 1);
                        if (r0 < PW)
                            *reinterpret_cast<float2*>(obase + r0 * DD + col) =
                                make_float2(acc[mt][nt][0], acc[mt][nt][1]);
                        if (r0 + 8 < PW)
                            *reinterpret_cast<float2*>(obase + (r0 + 8) * DD + col) =
                                make_float2(acc[mt][nt][2], acc[mt][nt][3]);
                    }
                }
            }
        }
    }
}

extern "C" void kernel_launch(void* const* d_in, const int* in_sizes, int n_in,
                              void* d_out, int out_size)
{
    const float* x      = (const float*)d_in[0];
    const float* Wqkv   = (const float*)d_in[1];
    const float* bqkv   = (const float*)d_in[2];
    const float* Wmerge = (const float*)d_in[3];
    const float* bmerge = (const float*)d_in[4];
    const float* table  = (const float*)d_in[5];
    float* out = (float*)d_out;

    const int nwin = in_sizes[0] / (PW * DD);   // 16384

    int sms = 148;
    cudaDeviceGetAttribute(&sms, cudaDevAttrMultiProcessorCount, 0);

    cudaFuncSetAttribute(rpmha_dual_kernel,
                         cudaFuncAttributeMaxDynamicSharedMemorySize, SMEM_BYTES);
    rpmha_dual_kernel<<<sms, 512, SMEM_BYTES>>>(x, Wqkv, bqkv, Wmerge, bmerge,
                                                table, out, nwin);
}

// round 10
// speedup vs baseline: 1.0029x; 1.0029x over previous
#include <cuda_runtime.h>
#include <cuda_fp16.h>
#include <cstdint>
#include <math.h>

#define PW 49
#define DD 128

// ---------------- smem layout (halfs) ----------------
// wq   [128][392] : resident Wqkv fp16
// wm   [128][136] : resident Wmerge fp16
// buf: Q rows 0..55 | K rows 56..111 | V rows 112..175  (pitch 136)
//      V doubles as x staging; Q doubles as attn-out.
// bias [4][49][56] fp16 : precomputed rel-pos bias, j-mask baked in (-60000)
static constexpr int WQ_P = 392;
static constexpr int WM_P = 136;
static constexpr int BP   = 136;
static constexpr int WQ_OFF  = 0;
static constexpr int WM_OFF  = 128 * WQ_P;             // 50176
static constexpr int BUF_OFF = WM_OFF + 128 * WM_P;    // 67584
static constexpr int K_ROFF  = 56 * BP;
static constexpr int V_ROFF  = 112 * BP;
static constexpr int BIAS_OFF = BUF_OFF + 176 * BP;    // 91520
static constexpr int BIAS_P  = 56;
static constexpr int HALFS   = BIAS_OFF + 4 * 49 * BIAS_P;   // 102496
static constexpr int SMEM_BYTES = HALFS * 2;           // 204992

__device__ __forceinline__ uint32_t cvta_s(const void* p)
{
    return (uint32_t)__cvta_generic_to_shared(p);
}
__device__ __forceinline__ uint32_t f2h2(float a, float b)
{
    __half2 h = __floats2half2_rn(a, b);
    return *reinterpret_cast<uint32_t*>(&h);
}

#define LDSM4(R0,R1,R2,R3,ADDR) \
    asm volatile("ldmatrix.sync.aligned.m8n8.x4.shared.b16 {%0,%1,%2,%3},[%4];" \
        : "=r"(R0),"=r"(R1),"=r"(R2),"=r"(R3) : "r"(ADDR))
#define LDSM4T(R0,R1,R2,R3,ADDR) \
    asm volatile("ldmatrix.sync.aligned.m8n8.x4.trans.shared.b16 {%0,%1,%2,%3},[%4];" \
        : "=r"(R0),"=r"(R1),"=r"(R2),"=r"(R3) : "r"(ADDR))
#define MMA(C0,C1,C2,C3,A0,A1,A2,A3,B0,B1) \
    asm volatile("mma.sync.aligned.m16n8k16.row.col.f32.f16.f16.f32 " \
        "{%0,%1,%2,%3},{%4,%5,%6,%7},{%8,%9},{%0,%1,%2,%3};" \
        : "+f"(C0),"+f"(C1),"+f"(C2),"+f"(C3) \
        : "r"(A0),"r"(A1),"r"(A2),"r"(A3),"r"(B0),"r"(B1))

__global__ void __launch_bounds__(256, 1)
rpmha_bias_kernel(const float* __restrict__ x,
                  const float* __restrict__ Wqkv,
                  const float* __restrict__ bqkv,
                  const float* __restrict__ Wmerge,
                  const float* __restrict__ bmerge,
                  const float* __restrict__ table,
                  float* __restrict__ out, int nwin)
{
    extern __shared__ __half sh[];
    __half* wq   = sh + WQ_OFF;
    __half* wm   = sh + WM_OFF;
    __half* bufQ = sh + BUF_OFF;
    __half* bufK = bufQ + K_ROFF;
    __half* bufV = bufQ + V_ROFF;
    __half* bias = sh + BIAS_OFF;

    const int tid = threadIdx.x, warp = tid >> 5, lane = tid & 31;
    const uint32_t q_s  = cvta_s(bufQ);
    const uint32_t k_s  = cvta_s(bufK);
    const uint32_t v_s  = cvta_s(bufV);
    const uint32_t wq_s = cvta_s(wq);
    const uint32_t wm_s = cvta_s(wm);
    const float scale = 0.17677669529663687f;  // 1/sqrt(32)

    // GEMM warp split: 2 (M) x 4 (N)
    const int wrow = (warp & 1) << 5;        // 0 / 32
    const int wq0  = (warp >> 1) * 96;       // phase-1 col base
    const int wc   = (warp >> 1) << 5;       // phase-3 col base
    // attention: 2 warps per head
    const int ah = warp & 3, amh = warp >> 2;

    // ---- one-time init ----
    {
        uint2* bz = reinterpret_cast<uint2*>(bufQ);
        for (int i = tid; i < 176 * BP / 4; i += 256) bz[i] = make_uint2(0u, 0u);
        for (int i = tid; i < 128 * 384; i += 256) {
            int r = i / 384, c = i - r * 384;
            wq[r * WQ_P + c] = __float2half_rn(Wqkv[i]);
        }
        for (int i = tid; i < 128 * 128; i += 256) {
            int r = i >> 7, c = i & 127;
            wm[r * WM_P + c] = __float2half_rn(Wmerge[i]);
        }
        // masked bias table: bias[h][i][j], j>=49 -> -60000 (kills softmax)
        for (int t = tid; t < 4 * 49 * BIAS_P; t += 256) {
            int h = t / (49 * BIAS_P);
            int rem = t - h * 49 * BIAS_P;
            int i = rem / BIAS_P, j = rem - i * BIAS_P;
            float v = -60000.0f;
            if (j < PW) {
                int ri = i / 7, ci = i - ri * 7;
                int rj = j / 7, cj = j - rj * 7;
                v = __ldg(table + (((ri - rj + 6) * 13) + (ci - cj + 6)) * 4 + h);
            }
            bias[t] = __float2half_rn(v);
        }
    }
    __syncthreads();

    // x loader: fp32 global -> fp16 V rows 0..48 (pads stay zero)
    auto load_x = [&](int w) {
        const float* src = x + (size_t)w * (PW * DD);
        #pragma unroll
        for (int t = 0; t < 7; t++) {
            int idx = tid + t * 256;
            if (idx < PW * 32) {
                int row = idx >> 5, c4 = (idx & 31) << 2;
                float4 f = __ldg(reinterpret_cast<const float4*>(src + row * DD + c4));
                uint2 st; st.x = f2h2(f.x, f.y); st.y = f2h2(f.z, f.w);
                *reinterpret_cast<uint2*>(bufV + row * BP + c4) = st;
            }
        }
    };

    int win = blockIdx.x;
    if (win < nwin) load_x(win);

    for (; win < nwin; win += gridDim.x) {
        __syncthreads();                   // (1) x in V; prev phase-3 done

        // ---- A fragments: x rows wrow..wrow+31 from V ----
        uint32_t af[2][8][4];
        #pragma unroll
        for (int mt = 0; mt < 2; mt++) {
            uint32_t a0 = v_s + (((wrow + mt * 16) + (lane & 15)) * BP
                                 + ((lane >> 4) << 3)) * 2;
            #pragma unroll
            for (int kk = 0; kk < 8; kk++)
                LDSM4(af[mt][kk][0], af[mt][kk][1], af[mt][kk][2], af[mt][kk][3],
                      a0 + kk * 32);
        }
        __syncthreads();                   // (2) A captured; V writable

        // ================= Phase 1: qkv = x @ Wqkv + bqkv =================
        #pragma unroll
        for (int p = 0; p < 6; p++) {
            const int c0 = wq0 + p * 16;
            float acc[2][2][4];
            #pragma unroll
            for (int nt = 0; nt < 2; nt++) {
                int col = c0 + nt * 8 + ((lane & 3) << 1);
                float b0 = __ldg(bqkv + col), b1 = __ldg(bqkv + col + 1);
                #pragma unroll
                for (int mt = 0; mt < 2; mt++) {
                    acc[mt][nt][0] = b0; acc[mt][nt][1] = b1;
                    acc[mt][nt][2] = b0; acc[mt][nt][3] = b1;
                }
            }
            uint32_t wb0 = wq_s + ((lane & 15) * WQ_P + c0 + ((lane >> 4) << 3)) * 2;
            #pragma unroll
            for (int kk = 0; kk < 8; kk++) {
                uint32_t b[4];
                LDSM4T(b[0], b[1], b[2], b[3], wb0 + (kk * 16 * WQ_P) * 2);
                #pragma unroll
                for (int mt = 0; mt < 2; mt++) {
                    MMA(acc[mt][0][0],acc[mt][0][1],acc[mt][0][2],acc[mt][0][3],
                        af[mt][kk][0],af[mt][kk][1],af[mt][kk][2],af[mt][kk][3],
                        b[0], b[1]);
                    MMA(acc[mt][1][0],acc[mt][1][1],acc[mt][1][2],acc[mt][1][3],
                        af[mt][kk][0],af[mt][kk][1],af[mt][kk][2],af[mt][kk][3],
                        b[2], b[3]);
                }
            }
            const float mul = (c0 < 128) ? scale : 1.0f;
            __half* dstb = (c0 < 128) ? (bufQ + c0)
                        : (c0 < 256) ? (bufK + c0 - 128)
                                     : (bufV + c0 - 256);
            #pragma unroll
            for (int mt = 0; mt < 2; mt++) {
                const int r0 = wrow + mt * 16 + (lane >> 2);
                #pragma unroll
                for (int nt = 0; nt < 2; nt++) {
                    int cl = nt * 8 + ((lane & 3) << 1);
                    if (r0 < PW)
                        *reinterpret_cast<__half2*>(dstb + r0 * BP + cl) =
                            __floats2half2_rn(acc[mt][nt][0] * mul, acc[mt][nt][1] * mul);
                    if (r0 + 8 < PW)
                        *reinterpret_cast<__half2*>(dstb + (r0 + 8) * BP + cl) =
                            __floats2half2_rn(acc[mt][nt][2] * mul, acc[mt][nt][3] * mul);
                }
            }
        }
        __syncthreads();                   // (3) qkv ready

        // ============ Phase 2: attention (2 warps per head) ============
        {
            const int h = ah;
            uint32_t kb[7][4];
            #pragma unroll
            for (int nt = 0; nt < 7; nt++) {
                uint32_t addr = k_s + ((nt * 8 + (lane & 7)) * BP
                                       + h * 32 + ((lane >> 3) << 3)) * 2;
                LDSM4(kb[nt][0], kb[nt][1], kb[nt][2], kb[nt][3], addr);
            }
            uint32_t vbr[4][8];
            #pragma unroll
            for (int kt = 0; kt < 4; kt++)
                #pragma unroll
                for (int dp = 0; dp < 2; dp++) {
                    uint32_t addr = v_s + ((kt * 16 + (lane & 15)) * BP
                                           + h * 32 + dp * 16 + ((lane >> 4) << 3)) * 2;
                    LDSM4T(vbr[kt][dp*4+0], vbr[kt][dp*4+1],
                           vbr[kt][dp*4+2], vbr[kt][dp*4+3], addr);
                }

            const __half* bh = bias + h * 49 * BIAS_P + ((lane & 3) << 1);

            #pragma unroll
            for (int mi = 0; mi < 2; mi++) {
                const int m = amh * 2 + mi;
                uint32_t qa[4], qa2[4];
                uint32_t qaddr = q_s + ((m * 16 + (lane & 15)) * BP
                                        + h * 32 + ((lane >> 4) << 3)) * 2;
                LDSM4(qa[0], qa[1], qa[2], qa[3], qaddr);
                LDSM4(qa2[0], qa2[1], qa2[2], qa2[3], qaddr + 32);

                float s[7][4];
                #pragma unroll
                for (int nt = 0; nt < 7; nt++) {
                    s[nt][0] = s[nt][1] = s[nt][2] = s[nt][3] = 0.f;
                    MMA(s[nt][0],s[nt][1],s[nt][2],s[nt][3],
                        qa[0],qa[1],qa[2],qa[3], kb[nt][0], kb[nt][1]);
                    MMA(s[nt][0],s[nt][1],s[nt][2],s[nt][3],
                        qa2[0],qa2[1],qa2[2],qa2[3], kb[nt][2], kb[nt][3]);
                }

                // bias + mask in one fp16 smem table (chain-light)
                int i0 = m * 16 + (lane >> 2), i1 = i0 + 8;
                int i0c = (i0 < PW) ? i0 : 0, i1c = (i1 < PW) ? i1 : 0;
                const __half* bp0 = bh + i0c * BIAS_P;
                const __half* bp1 = bh + i1c * BIAS_P;
                #pragma unroll
                for (int nt = 0; nt < 7; nt++) {
                    float2 b0 = __half22float2(
                        *reinterpret_cast<const __half2*>(bp0 + nt * 8));
                    float2 b1 = __half22float2(
                        *reinterpret_cast<const __half2*>(bp1 + nt * 8));
                    s[nt][0] += b0.x; s[nt][1] += b0.y;
                    s[nt][2] += b1.x; s[nt][3] += b1.y;
                }

                float ml = -1e30f, mh2 = -1e30f;
                #pragma unroll
                for (int nt = 0; nt < 7; nt++) {
                    ml  = fmaxf(ml,  fmaxf(s[nt][0], s[nt][1]));
                    mh2 = fmaxf(mh2, fmaxf(s[nt][2], s[nt][3]));
                }
                ml  = fmaxf(ml,  __shfl_xor_sync(0xffffffffu, ml, 1));
                ml  = fmaxf(ml,  __shfl_xor_sync(0xffffffffu, ml, 2));
                mh2 = fmaxf(mh2, __shfl_xor_sync(0xffffffffu, mh2, 1));
                mh2 = fmaxf(mh2, __shfl_xor_sync(0xffffffffu, mh2, 2));
                float sl = 0.f, shs = 0.f;
                #pragma unroll
                for (int nt = 0; nt < 7; nt++) {
                    s[nt][0] = __expf(s[nt][0] - ml);  sl  += s[nt][0];
                    s[nt][1] = __expf(s[nt][1] - ml);  sl  += s[nt][1];
                    s[nt][2] = __expf(s[nt][2] - mh2); shs += s[nt][2];
                    s[nt][3] = __expf(s[nt][3] - mh2); shs += s[nt][3];
                }
                sl  += __shfl_xor_sync(0xffffffffu, sl, 1);
                sl  += __shfl_xor_sync(0xffffffffu, sl, 2);
                shs += __shfl_xor_sync(0xffffffffu, shs, 1);
                shs += __shfl_xor_sync(0xffffffffu, shs, 2);
                const float il = 1.f / sl, ih = 1.f / shs;

                uint32_t pa[4][4];
                #pragma unroll
                for (int kt = 0; kt < 4; kt++) {
                    int n0 = 2 * kt, n1 = 2 * kt + 1;
                    pa[kt][0] = f2h2(s[n0][0] * il, s[n0][1] * il);
                    pa[kt][1] = f2h2(s[n0][2] * ih, s[n0][3] * ih);
                    if (n1 < 7) {
                        pa[kt][2] = f2h2(s[n1][0] * il, s[n1][1] * il);
                        pa[kt][3] = f2h2(s[n1][2] * ih, s[n1][3] * ih);
                    } else { pa[kt][2] = 0u; pa[kt][3] = 0u; }
                }

                float o[4][4];
                #pragma unroll
                for (int d = 0; d < 4; d++) o[d][0]=o[d][1]=o[d][2]=o[d][3]=0.f;
                #pragma unroll
                for (int kt = 0; kt < 4; kt++) {
                    MMA(o[0][0],o[0][1],o[0][2],o[0][3],
                        pa[kt][0],pa[kt][1],pa[kt][2],pa[kt][3], vbr[kt][0], vbr[kt][1]);
                    MMA(o[1][0],o[1][1],o[1][2],o[1][3],
                        pa[kt][0],pa[kt][1],pa[kt][2],pa[kt][3], vbr[kt][2], vbr[kt][3]);
                    MMA(o[2][0],o[2][1],o[2][2],o[2][3],
                        pa[kt][0],pa[kt][1],pa[kt][2],pa[kt][3], vbr[kt][4], vbr[kt][5]);
                    MMA(o[3][0],o[3][1],o[3][2],o[3][3],
                        pa[kt][0],pa[kt][1],pa[kt][2],pa[kt][3], vbr[kt][6], vbr[kt][7]);
                }
                const int orow = m * 16 + (lane >> 2);
                #pragma unroll
                for (int d = 0; d < 4; d++) {
                    int col = h * 32 + d * 8 + ((lane & 3) << 1);
                    if (orow < PW)
                        *reinterpret_cast<__half2*>(bufQ + orow * BP + col) =
                            __floats2half2_rn(o[d][0], o[d][1]);
                    if (orow + 8 < PW)
                        *reinterpret_cast<__half2*>(bufQ + (orow + 8) * BP + col) =
                            __floats2half2_rn(o[d][2], o[d][3]);
                }
            }
        }
        __syncthreads();                   // (4) attn-out ready; V free

        if (win + (int)gridDim.x < nwin) load_x(win + gridDim.x);

        // ============ Phase 3: out = attn_out @ Wmerge + bmerge ============
        {
            uint32_t af2[2][8][4];
            #pragma unroll
            for (int mt = 0; mt < 2; mt++) {
                uint32_t a0 = q_s + (((wrow + mt * 16) + (lane & 15)) * BP
                                     + ((lane >> 4) << 3)) * 2;
                #pragma unroll
                for (int kk = 0; kk < 8; kk++)
                    LDSM4(af2[mt][kk][0], af2[mt][kk][1], af2[mt][kk][2], af2[mt][kk][3],
                          a0 + kk * 32);
            }
            float* obase = out + (size_t)win * (PW * DD);

            #pragma unroll
            for (int nh = 0; nh < 2; nh++) {
                const int c0 = wc + nh * 16;
                float acc[2][2][4];
                #pragma unroll
                for (int nt = 0; nt < 2; nt++) {
                    int col = c0 + nt * 8 + ((lane & 3) << 1);
                    float b0 = __ldg(bmerge + col), b1 = __ldg(bmerge + col + 1);
                    #pragma unroll
                    for (int mt = 0; mt < 2; mt++) {
                        acc[mt][nt][0] = b0; acc[mt][nt][1] = b1;
                        acc[mt][nt][2] = b0; acc[mt][nt][3] = b1;
                    }
                }
                uint32_t wm0 = wm_s + ((lane & 15) * WM_P + c0 + ((lane >> 4) << 3)) * 2;
                #pragma unroll
                for (int kk = 0; kk < 8; kk++) {
                    uint32_t b[4];
                    LDSM4T(b[0], b[1], b[2], b[3], wm0 + (kk * 16 * WM_P) * 2);
                    #pragma unroll
                    for (int mt = 0; mt < 2; mt++) {
                        MMA(acc[mt][0][0],acc[mt][0][1],acc[mt][0][2],acc[mt][0][3],
                            af2[mt][kk][0],af2[mt][kk][1],af2[mt][kk][2],af2[mt][kk][3],
                            b[0], b[1]);
                        MMA(acc[mt][1][0],acc[mt][1][1],acc[mt][1][2],acc[mt][1][3],
                            af2[mt][kk][0],af2[mt][kk][1],af2[mt][kk][2],af2[mt][kk][3],
                            b[2], b[3]);
                    }
                }
                #pragma unroll
                for (int mt = 0; mt < 2; mt++) {
                    const int r0 = wrow + mt * 16 + (lane >> 2);
                    #pragma unroll
                    for (int nt = 0; nt < 2; nt++) {
                        int col = c0 + nt * 8 + ((lane & 3) << 1);
                        if (r0 < PW)
                            *reinterpret_cast<float2*>(obase + r0 * DD + col) =
                                make_float2(acc[mt][nt][0], acc[mt][nt][1]);
                        if (r0 + 8 < PW)
                            *reinterpret_cast<float2*>(obase + (r0 + 8) * DD + col) =
                                make_float2(acc[mt][nt][2], acc[mt][nt][3]);
                    }
                }
            }
        }
    }
}

extern "C" void kernel_launch(void* const* d_in, const int* in_sizes, int n_in,
                              void* d_out, int out_size)
{
    const float* x      = (const float*)d_in[0];
    const float* Wqkv   = (const float*)d_in[1];
    const float* bqkv   = (const float*)d_in[2];
    const float* Wmerge = (const float*)d_in[3];
    const float* bmerge = (const float*)d_in[4];
    const float* table  = (const float*)d_in[5];
    float* out = (float*)d_out;

    const int nwin = in_sizes[0] / (PW * DD);   // 16384

    int sms = 148;
    cudaDeviceGetAttribute(&sms, cudaDevAttrMultiProcessorCount, 0);

    cudaFuncSetAttribute(rpmha_bias_kernel,
                         cudaFuncAttributeMaxDynamicSharedMemorySize, SMEM_BYTES);
    rpmha_bias_kernel<<<sms, 256, SMEM_BYTES>>>(x, Wqkv, bqkv, Wmerge, bmerge,
                                                table, out, nwin);
}

// round 11
// speedup vs baseline: 1.0733x; 1.0702x over previous
#include <cuda_runtime.h>
#include <cuda_fp16.h>
#include <cstdint>
#include <math.h>

#define PW 49
#define DD 128

// masked rel-pos bias, fp16, [4 heads][49 i][56 j] (j>=49 -> -60000)
__device__ __half g_bias[4 * 49 * 56];

__global__ void prep_bias_kernel(const float* __restrict__ table)
{
    int t = blockIdx.x * 256 + threadIdx.x;
    if (t >= 4 * 49 * 56) return;
    int h = t / (49 * 56);
    int rem = t - h * (49 * 56);
    int i = rem / 56, j = rem - i * 56;
    float v = -60000.0f;
    if (j < PW) {
        int ri = i / 7, ci = i - ri * 7;
        int rj = j / 7, cj = j - rj * 7;
        v = table[(((ri - rj + 6) * 13) + (ci - cj + 6)) * 4 + h];
    }
    g_bias[t] = __float2half_rn(v);
}

// ---------------- smem layout (halfs) ----------------
// wq  [128][392] : resident Wqkv fp16 (shared by both groups)
// wm  [128][136] : resident Wmerge fp16
// buf[g] (g=0,1): Q rows 0..55 | K rows 56..111 | V rows 112..175, pitch 136.
//   V doubles as x staging; Q doubles as attn-out. Pad rows zeroed once,
//   stores guarded row<49 so they stay zero.
static constexpr int WQ_P = 392;
static constexpr int WM_P = 136;
static constexpr int BP   = 136;
static constexpr int WQ_OFF  = 0;
static constexpr int WM_OFF  = 128 * WQ_P;             // 50176
static constexpr int BUF_OFF = WM_OFF + 128 * WM_P;    // 67584
static constexpr int K_ROFF  = 56 * BP;
static constexpr int V_ROFF  = 112 * BP;
static constexpr int BUF_SZ  = 176 * BP;               // 23936
static constexpr int HALFS   = BUF_OFF + 2 * BUF_SZ;   // 115456
static constexpr int SMEM_BYTES = HALFS * 2;           // 230912

__device__ __forceinline__ uint32_t cvta_s(const void* p)
{
    return (uint32_t)__cvta_generic_to_shared(p);
}
__device__ __forceinline__ uint32_t f2h2(float a, float b)
{
    __half2 h = __floats2half2_rn(a, b);
    return *reinterpret_cast<uint32_t*>(&h);
}
__device__ __forceinline__ void gbar(int id)
{
    asm volatile("bar.sync %0, %1;" :: "r"(id), "r"(256) : "memory");
}

#define LDSM4(R0,R1,R2,R3,ADDR) \
    asm volatile("ldmatrix.sync.aligned.m8n8.x4.shared.b16 {%0,%1,%2,%3},[%4];" \
        : "=r"(R0),"=r"(R1),"=r"(R2),"=r"(R3) : "r"(ADDR))
#define LDSM4T(R0,R1,R2,R3,ADDR) \
    asm volatile("ldmatrix.sync.aligned.m8n8.x4.trans.shared.b16 {%0,%1,%2,%3},[%4];" \
        : "=r"(R0),"=r"(R1),"=r"(R2),"=r"(R3) : "r"(ADDR))
#define MMA(C0,C1,C2,C3,A0,A1,A2,A3,B0,B1) \
    asm volatile("mma.sync.aligned.m16n8k16.row.col.f32.f16.f16.f32 " \
        "{%0,%1,%2,%3},{%4,%5,%6,%7},{%8,%9},{%0,%1,%2,%3};" \
        : "+f"(C0),"+f"(C1),"+f"(C2),"+f"(C3) \
        : "r"(A0),"r"(A1),"r"(A2),"r"(A3),"r"(B0),"r"(B1))

__global__ void __launch_bounds__(512, 1)
rpmha_dual2_kernel(const float* __restrict__ x,
                   const float* __restrict__ Wqkv,
                   const float* __restrict__ bqkv,
                   const float* __restrict__ Wmerge,
                   const float* __restrict__ bmerge,
                   float* __restrict__ out, int nwin)
{
    extern __shared__ __half sh[];
    __half* wq = sh + WQ_OFF;
    __half* wm = sh + WM_OFF;

    const int tid = threadIdx.x, warp = tid >> 5, lane = tid & 31;
    const int g    = warp >> 3;        // window group 0/1
    const int lw   = warp & 7;         // warp within group
    const int gtid = tid & 255;
    const int bid  = g + 1;            // named barrier id

    __half* bufQ = sh + BUF_OFF + g * BUF_SZ;
    __half* bufK = bufQ + K_ROFF;
    __half* bufV = bufQ + V_ROFF;
    const uint32_t q_s  = cvta_s(bufQ);
    const uint32_t k_s  = cvta_s(bufK);
    const uint32_t v_s  = cvta_s(bufV);
    const uint32_t wq_s = cvta_s(wq);
    const uint32_t wm_s = cvta_s(wm);
    const float scale = 0.17677669529663687f;  // 1/sqrt(32)

    // GEMM split: 4 (M) x 2 (N) -> one m-tile of A per warp (32 regs)
    const int wrow = (lw & 3) << 4;          // 0/16/32/48
    const int n2   = lw >> 2;                // 0/1
    // attention: 2 warps per head
    const int ah = lw & 3, amh = lw >> 2;

    // ---- one-time init: zero both buffers, load resident weights ----
    {
        uint2* bz = reinterpret_cast<uint2*>(sh + BUF_OFF);
        for (int i = tid; i < 2 * BUF_SZ / 4; i += 512) bz[i] = make_uint2(0u, 0u);
        for (int i = tid; i < 128 * 384; i += 512) {
            int r = i / 384, c = i - r * 384;
            wq[r * WQ_P + c] = __float2half_rn(Wqkv[i]);
        }
        for (int i = tid; i < 128 * 128; i += 512) {
            int r = i >> 7, c = i & 127;
            wm[r * WM_P + c] = __float2half_rn(Wmerge[i]);
        }
    }
    __syncthreads();

    const int stride = 2 * gridDim.x;
    int win = blockIdx.x * 2 + g;

    // x loader: fp32 global -> fp16 V rows 0..48 (pads stay zero)
    auto load_x = [&](int w) {
        const float* src = x + (size_t)w * (PW * DD);
        #pragma unroll
        for (int t = 0; t < 7; t++) {
            int idx = gtid + t * 256;
            if (idx < PW * 32) {
                int row = idx >> 5, c4 = (idx & 31) << 2;
                float4 f = __ldg(reinterpret_cast<const float4*>(src + row * DD + c4));
                uint2 st; st.x = f2h2(f.x, f.y); st.y = f2h2(f.z, f.w);
                *reinterpret_cast<uint2*>(bufV + row * BP + c4) = st;
            }
        }
    };

    if (win < nwin) load_x(win);

    for (; win < nwin; win += stride) {
        gbar(bid);                         // (1) x in V; prev phase-3 done

        // ---- A fragments: x rows wrow..wrow+15 from V ----
        uint32_t af[8][4];
        {
            uint32_t a0 = v_s + ((wrow + (lane & 15)) * BP + ((lane >> 4) << 3)) * 2;
            #pragma unroll
            for (int kk = 0; kk < 8; kk++)
                LDSM4(af[kk][0], af[kk][1], af[kk][2], af[kk][3], a0 + kk * 32);
        }
        gbar(bid);                         // (2) A captured; V writable

        // ================= Phase 1: qkv = x @ Wqkv + bqkv =================
        #pragma unroll
        for (int p = 0; p < 12; p++) {
            const int c0 = n2 * 192 + p * 16;
            float acc[2][4];
            #pragma unroll
            for (int nt = 0; nt < 2; nt++) {
                int col = c0 + nt * 8 + ((lane & 3) << 1);
                float b0 = __ldg(bqkv + col), b1 = __ldg(bqkv + col + 1);
                acc[nt][0] = b0; acc[nt][1] = b1;
                acc[nt][2] = b0; acc[nt][3] = b1;
            }
            uint32_t wb0 = wq_s + ((lane & 15) * WQ_P + c0 + ((lane >> 4) << 3)) * 2;
            #pragma unroll
            for (int kk = 0; kk < 8; kk++) {
                uint32_t b[4];
                LDSM4T(b[0], b[1], b[2], b[3], wb0 + (kk * 16 * WQ_P) * 2);
                MMA(acc[0][0],acc[0][1],acc[0][2],acc[0][3],
                    af[kk][0],af[kk][1],af[kk][2],af[kk][3], b[0], b[1]);
                MMA(acc[1][0],acc[1][1],acc[1][2],acc[1][3],
                    af[kk][0],af[kk][1],af[kk][2],af[kk][3], b[2], b[3]);
            }
            const float mul = (c0 < 128) ? scale : 1.0f;
            __half* dstb = (c0 < 128) ? (bufQ + c0)
                        : (c0 < 256) ? (bufK + c0 - 128)
                                     : (bufV + c0 - 256);
            const int r0 = wrow + (lane >> 2);
            #pragma unroll
            for (int nt = 0; nt < 2; nt++) {
                int cl = nt * 8 + ((lane & 3) << 1);
                if (r0 < PW)
                    *reinterpret_cast<__half2*>(dstb + r0 * BP + cl) =
                        __floats2half2_rn(acc[nt][0] * mul, acc[nt][1] * mul);
                if (r0 + 8 < PW)
                    *reinterpret_cast<__half2*>(dstb + (r0 + 8) * BP + cl) =
                        __floats2half2_rn(acc[nt][2] * mul, acc[nt][3] * mul);
            }
        }
        gbar(bid);                         // (3) qkv ready

        // ============ Phase 2: attention (2 warps per head) ============
        {
            const int h = ah;
            uint32_t kb[7][4];
            #pragma unroll
            for (int nt = 0; nt < 7; nt++) {
                uint32_t addr = k_s + ((nt * 8 + (lane & 7)) * BP
                                       + h * 32 + ((lane >> 3) << 3)) * 2;
                LDSM4(kb[nt][0], kb[nt][1], kb[nt][2], kb[nt][3], addr);
            }
            const __half* bh = g_bias + h * (49 * 56) + ((lane & 3) << 1);

            #pragma unroll
            for (int mi = 0; mi < 2; mi++) {
                const int m = amh * 2 + mi;
                uint32_t qa[4], qa2[4];
                uint32_t qaddr = q_s + ((m * 16 + (lane & 15)) * BP
                                        + h * 32 + ((lane >> 4) << 3)) * 2;
                LDSM4(qa[0], qa[1], qa[2], qa[3], qaddr);
                LDSM4(qa2[0], qa2[1], qa2[2], qa2[3], qaddr + 32);

                float s[7][4];
                #pragma unroll
                for (int nt = 0; nt < 7; nt++) {
                    s[nt][0] = s[nt][1] = s[nt][2] = s[nt][3] = 0.f;
                    MMA(s[nt][0],s[nt][1],s[nt][2],s[nt][3],
                        qa[0],qa[1],qa[2],qa[3], kb[nt][0], kb[nt][1]);
                    MMA(s[nt][0],s[nt][1],s[nt][2],s[nt][3],
                        qa2[0],qa2[1],qa2[2],qa2[3], kb[nt][2], kb[nt][3]);
                }

                // bias + mask from precomputed fp16 table (L1-resident)
                int i0 = m * 16 + (lane >> 2), i1 = i0 + 8;
                int i0c = (i0 < PW) ? i0 : 0, i1c = (i1 < PW) ? i1 : 0;
                const __half* bp0 = bh + i0c * 56;
                const __half* bp1 = bh + i1c * 56;
                #pragma unroll
                for (int nt = 0; nt < 7; nt++) {
                    float2 b0 = __half22float2(
                        __ldg(reinterpret_cast<const __half2*>(bp0 + nt * 8)));
                    float2 b1 = __half22float2(
                        __ldg(reinterpret_cast<const __half2*>(bp1 + nt * 8)));
                    s[nt][0] += b0.x; s[nt][1] += b0.y;
                    s[nt][2] += b1.x; s[nt][3] += b1.y;
                }

                float ml = -1e30f, mh2 = -1e30f;
                #pragma unroll
                for (int nt = 0; nt < 7; nt++) {
                    ml  = fmaxf(ml,  fmaxf(s[nt][0], s[nt][1]));
                    mh2 = fmaxf(mh2, fmaxf(s[nt][2], s[nt][3]));
                }
                ml  = fmaxf(ml,  __shfl_xor_sync(0xffffffffu, ml, 1));
                ml  = fmaxf(ml,  __shfl_xor_sync(0xffffffffu, ml, 2));
                mh2 = fmaxf(mh2, __shfl_xor_sync(0xffffffffu, mh2, 1));
                mh2 = fmaxf(mh2, __shfl_xor_sync(0xffffffffu, mh2, 2));
                float sl = 0.f, shs = 0.f;
                #pragma unroll
                for (int nt = 0; nt < 7; nt++) {
                    s[nt][0] = __expf(s[nt][0] - ml);  sl  += s[nt][0];
                    s[nt][1] = __expf(s[nt][1] - ml);  sl  += s[nt][1];
                    s[nt][2] = __expf(s[nt][2] - mh2); shs += s[nt][2];
                    s[nt][3] = __expf(s[nt][3] - mh2); shs += s[nt][3];
                }
                sl  += __shfl_xor_sync(0xffffffffu, sl, 1);
                sl  += __shfl_xor_sync(0xffffffffu, sl, 2);
                shs += __shfl_xor_sync(0xffffffffu, shs, 1);
                shs += __shfl_xor_sync(0xffffffffu, shs, 2);
                const float il = 1.f / sl, ih = 1.f / shs;

                uint32_t pa[4][4];
                #pragma unroll
                for (int kt = 0; kt < 4; kt++) {
                    int n0 = 2 * kt, n1 = 2 * kt + 1;
                    pa[kt][0] = f2h2(s[n0][0] * il, s[n0][1] * il);
                    pa[kt][1] = f2h2(s[n0][2] * ih, s[n0][3] * ih);
                    if (n1 < 7) {
                        pa[kt][2] = f2h2(s[n1][0] * il, s[n1][1] * il);
                        pa[kt][3] = f2h2(s[n1][2] * ih, s[n1][3] * ih);
                    } else { pa[kt][2] = 0u; pa[kt][3] = 0u; }
                }

                float o[4][4];
                #pragma unroll
                for (int d = 0; d < 4; d++) o[d][0]=o[d][1]=o[d][2]=o[d][3]=0.f;
                #pragma unroll
                for (int kt = 0; kt < 4; kt++) {
                    uint32_t vb[8];            // transient (reg-pressure cap)
                    #pragma unroll
                    for (int dp = 0; dp < 2; dp++) {
                        uint32_t addr = v_s + ((kt * 16 + (lane & 15)) * BP
                                               + h * 32 + dp * 16 + ((lane >> 4) << 3)) * 2;
                        LDSM4T(vb[dp*4+0], vb[dp*4+1], vb[dp*4+2], vb[dp*4+3], addr);
                    }
                    MMA(o[0][0],o[0][1],o[0][2],o[0][3],
                        pa[kt][0],pa[kt][1],pa[kt][2],pa[kt][3], vb[0], vb[1]);
                    MMA(o[1][0],o[1][1],o[1][2],o[1][3],
                        pa[kt][0],pa[kt][1],pa[kt][2],pa[kt][3], vb[2], vb[3]);
                    MMA(o[2][0],o[2][1],o[2][2],o[2][3],
                        pa[kt][0],pa[kt][1],pa[kt][2],pa[kt][3], vb[4], vb[5]);
                    MMA(o[3][0],o[3][1],o[3][2],o[3][3],
                        pa[kt][0],pa[kt][1],pa[kt][2],pa[kt][3], vb[6], vb[7]);
                }
                const int orow = m * 16 + (lane >> 2);
                #pragma unroll
                for (int d = 0; d < 4; d++) {
                    int col = h * 32 + d * 8 + ((lane & 3) << 1);
                    if (orow < PW)
                        *reinterpret_cast<__half2*>(bufQ + orow * BP + col) =
                            __floats2half2_rn(o[d][0], o[d][1]);
                    if (orow + 8 < PW)
                        *reinterpret_cast<__half2*>(bufQ + (orow + 8) * BP + col) =
                            __floats2half2_rn(o[d][2], o[d][3]);
                }
            }
        }
        gbar(bid);                         // (4) attn-out ready; V free

        if (win + stride < nwin) load_x(win + stride);   // overlaps phase 3

        // ============ Phase 3: out = attn_out @ Wmerge + bmerge ============
        {
            uint32_t af2[8][4];
            {
                uint32_t a0 = q_s + ((wrow + (lane & 15)) * BP
                                     + ((lane >> 4) << 3)) * 2;
                #pragma unroll
                for (int kk = 0; kk < 8; kk++)
                    LDSM4(af2[kk][0], af2[kk][1], af2[kk][2], af2[kk][3],
                          a0 + kk * 32);
            }
            float* obase = out + (size_t)win * (PW * DD);
            const int r0 = wrow + (lane >> 2);

            #pragma unroll
            for (int nh = 0; nh < 4; nh++) {
                const int c0 = n2 * 64 + nh * 16;
                float acc[2][4];
                #pragma unroll
                for (int nt = 0; nt < 2; nt++) {
                    int col = c0 + nt * 8 + ((lane & 3) << 1);
                    float b0 = __ldg(bmerge + col), b1 = __ldg(bmerge + col + 1);
                    acc[nt][0] = b0; acc[nt][1] = b1;
                    acc[nt][2] = b0; acc[nt][3] = b1;
                }
                uint32_t wm0 = wm_s + ((lane & 15) * WM_P + c0 + ((lane >> 4) << 3)) * 2;
                #pragma unroll
                for (int kk = 0; kk < 8; kk++) {
                    uint32_t b[4];
                    LDSM4T(b[0], b[1], b[2], b[3], wm0 + (kk * 16 * WM_P) * 2);
                    MMA(acc[0][0],acc[0][1],acc[0][2],acc[0][3],
                        af2[kk][0],af2[kk][1],af2[kk][2],af2[kk][3], b[0], b[1]);
                    MMA(acc[1][0],acc[1][1],acc[1][2],acc[1][3],
                        af2[kk][0],af2[kk][1],af2[kk][2],af2[kk][3], b[2], b[3]);
                }
                #pragma unroll
                for (int nt = 0; nt < 2; nt++) {
                    int col = c0 + nt * 8 + ((lane & 3) << 1);
                    if (r0 < PW)
                        *reinterpret_cast<float2*>(obase + r0 * DD + col) =
                            make_float2(acc[nt][0], acc[nt][1]);
                    if (r0 + 8 < PW)
                        *reinterpret_cast<float2*>(obase + (r0 + 8) * DD + col) =
                            make_float2(acc[nt][2], acc[nt][3]);
                }
            }
        }
    }
}

extern "C" void kernel_launch(void* const* d_in, const int* in_sizes, int n_in,
                              void* d_out, int out_size)
{
    const float* x      = (const float*)d_in[0];
    const float* Wqkv   = (const float*)d_in[1];
    const float* bqkv   = (const float*)d_in[2];
    const float* Wmerge = (const float*)d_in[3];
    const float* bmerge = (const float*)d_in[4];
    const float* table  = (const float*)d_in[5];
    float* out = (float*)d_out;

    const int nwin = in_sizes[0] / (PW * DD);   // 16384

    prep_bias_kernel<<<43, 256>>>(table);

    int sms = 148;
    cudaDeviceGetAttribute(&sms, cudaDevAttrMultiProcessorCount, 0);

    cudaFuncSetAttribute(rpmha_dual2_kernel,
                         cudaFuncAttributeMaxDynamicSharedMemorySize, SMEM_BYTES);
    rpmha_dual2_kernel<<<sms, 512, SMEM_BYTES>>>(x, Wqkv, bqkv, Wmerge, bmerge,
                                                 out, nwin);
}

// round 12
// speedup vs baseline: 1.1870x; 1.1059x over previous
#include <cuda_runtime.h>
#include <cuda_fp16.h>
#include <cstdint>
#include <math.h>

#define PW 49
#define DD 128

// masked rel-pos bias, fp16, [4 heads][49 i][56 j] (j>=49 -> -60000)
__device__ __half g_bias[4 * 49 * 56];

__global__ void prep_bias_kernel(const float* __restrict__ table)
{
    int t = blockIdx.x * 256 + threadIdx.x;
    if (t >= 4 * 49 * 56) return;
    int h = t / (49 * 56);
    int rem = t - h * (49 * 56);
    int i = rem / 56, j = rem - i * 56;
    float v = -60000.0f;
    if (j < PW) {
        int ri = i / 7, ci = i - ri * 7;
        int rj = j / 7, cj = j - rj * 7;
        v = table[(((ri - rj + 6) * 13) + (ci - cj + 6)) * 4 + h];
    }
    g_bias[t] = __float2half_rn(v);
}

// ---------------- smem layout (halfs) ----------------
// wq  [128][392] : resident Wqkv fp16 (shared by both groups)
// wm  [128][136] : resident Wmerge fp16
// buf[g] (g=0,1): Q rows 0..55 | K rows 56..111 | V rows 112..175, pitch 136.
//   V doubles as x staging; Q doubles as attn-out. Pad rows zeroed once,
//   stores guarded row<49 so they stay zero.
static constexpr int WQ_P = 392;
static constexpr int WM_P = 136;
static constexpr int BP   = 136;
static constexpr int WQ_OFF  = 0;
static constexpr int WM_OFF  = 128 * WQ_P;             // 50176
static constexpr int BUF_OFF = WM_OFF + 128 * WM_P;    // 67584
static constexpr int K_ROFF  = 56 * BP;
static constexpr int V_ROFF  = 112 * BP;
static constexpr int BUF_SZ  = 176 * BP;               // 23936
static constexpr int HALFS   = BUF_OFF + 2 * BUF_SZ;   // 115456
static constexpr int SMEM_BYTES = HALFS * 2;           // 230912

__device__ __forceinline__ uint32_t cvta_s(const void* p)
{
    return (uint32_t)__cvta_generic_to_shared(p);
}
__device__ __forceinline__ uint32_t f2h2(float a, float b)
{
    __half2 h = __floats2half2_rn(a, b);
    return *reinterpret_cast<uint32_t*>(&h);
}
__device__ __forceinline__ void gbar(int id)
{
    asm volatile("bar.sync %0, %1;" :: "r"(id), "r"(256) : "memory");
}

#define LDSM4(R0,R1,R2,R3,ADDR) \
    asm volatile("ldmatrix.sync.aligned.m8n8.x4.shared.b16 {%0,%1,%2,%3},[%4];" \
        : "=r"(R0),"=r"(R1),"=r"(R2),"=r"(R3) : "r"(ADDR))
#define LDSM4T(R0,R1,R2,R3,ADDR) \
    asm volatile("ldmatrix.sync.aligned.m8n8.x4.trans.shared.b16 {%0,%1,%2,%3},[%4];" \
        : "=r"(R0),"=r"(R1),"=r"(R2),"=r"(R3) : "r"(ADDR))
#define MMA(C0,C1,C2,C3,A0,A1,A2,A3,B0,B1) \
    asm volatile("mma.sync.aligned.m16n8k16.row.col.f32.f16.f16.f32 " \
        "{%0,%1,%2,%3},{%4,%5,%6,%7},{%8,%9},{%0,%1,%2,%3};" \
        : "+f"(C0),"+f"(C1),"+f"(C2),"+f"(C3) \
        : "r"(A0),"r"(A1),"r"(A2),"r"(A3),"r"(B0),"r"(B1))

__global__ void __launch_bounds__(512, 1)
rpmha_dual3_kernel(const float* __restrict__ x,
                   const float* __restrict__ Wqkv,
                   const float* __restrict__ bqkv,
                   const float* __restrict__ Wmerge,
                   const float* __restrict__ bmerge,
                   float* __restrict__ out, int nwin)
{
    extern __shared__ __half sh[];
    __half* wq = sh + WQ_OFF;
    __half* wm = sh + WM_OFF;

    const int tid = threadIdx.x, warp = tid >> 5, lane = tid & 31;
    const int g    = warp >> 3;        // window group 0/1
    const int lw   = warp & 7;         // warp within group
    const int gtid = tid & 255;
    const int bid  = g + 1;            // named barrier id

    __half* bufQ = sh + BUF_OFF + g * BUF_SZ;
    __half* bufK = bufQ + K_ROFF;
    __half* bufV = bufQ + V_ROFF;
    const uint32_t q_s  = cvta_s(bufQ);
    const uint32_t k_s  = cvta_s(bufK);
    const uint32_t v_s  = cvta_s(bufV);
    const uint32_t wq_s = cvta_s(wq);
    const uint32_t wm_s = cvta_s(wm);
    const float scale = 0.17677669529663687f;  // 1/sqrt(32)

    // GEMM split: 2 (M, two m-tiles each) x 4 (N) -> B fragments reused
    // across both m-tiles (half the ldmatrix traffic vs 4x2)
    const int wrow = (lw & 1) << 5;          // 0 / 32
    const int wq0  = (lw >> 1) * 96;         // phase-1 col base (96 cols)
    const int wc   = (lw >> 1) << 5;         // phase-3 col base (32 cols)
    // attention: 2 warps per head
    const int ah = lw & 3, amh = lw >> 2;

    // ---- one-time init: zero both buffers, load resident weights ----
    {
        uint2* bz = reinterpret_cast<uint2*>(sh + BUF_OFF);
        for (int i = tid; i < 2 * BUF_SZ / 4; i += 512) bz[i] = make_uint2(0u, 0u);
        for (int i = tid; i < 128 * 384; i += 512) {
            int r = i / 384, c = i - r * 384;
            wq[r * WQ_P + c] = __float2half_rn(Wqkv[i]);
        }
        for (int i = tid; i < 128 * 128; i += 512) {
            int r = i >> 7, c = i & 127;
            wm[r * WM_P + c] = __float2half_rn(Wmerge[i]);
        }
    }
    __syncthreads();

    const int stride = 2 * gridDim.x;
    int win = blockIdx.x * 2 + g;

    // x loader: fp32 global -> fp16 V rows 0..48 (pads stay zero)
    auto load_x = [&](int w) {
        const float* src = x + (size_t)w * (PW * DD);
        #pragma unroll
        for (int t = 0; t < 7; t++) {
            int idx = gtid + t * 256;
            if (idx < PW * 32) {
                int row = idx >> 5, c4 = (idx & 31) << 2;
                float4 f = __ldg(reinterpret_cast<const float4*>(src + row * DD + c4));
                uint2 st; st.x = f2h2(f.x, f.y); st.y = f2h2(f.z, f.w);
                *reinterpret_cast<uint2*>(bufV + row * BP + c4) = st;
            }
        }
    };

    if (win < nwin) load_x(win);

    for (; win < nwin; win += stride) {
        gbar(bid);                         // (1) x in V; prev phase-3 done

        // ---- A fragments: x rows wrow..wrow+31 (2 m-tiles) from V ----
        uint32_t af[2][8][4];
        #pragma unroll
        for (int mt = 0; mt < 2; mt++) {
            uint32_t a0 = v_s + (((wrow + mt * 16) + (lane & 15)) * BP
                                 + ((lane >> 4) << 3)) * 2;
            #pragma unroll
            for (int kk = 0; kk < 8; kk++)
                LDSM4(af[mt][kk][0], af[mt][kk][1], af[mt][kk][2], af[mt][kk][3],
                      a0 + kk * 32);
        }
        gbar(bid);                         // (2) A captured; V writable

        // ================= Phase 1: qkv = x @ Wqkv + bqkv =================
        #pragma unroll
        for (int p = 0; p < 6; p++) {
            const int c0 = wq0 + p * 16;
            float acc[2][2][4];
            #pragma unroll
            for (int nt = 0; nt < 2; nt++) {
                int col = c0 + nt * 8 + ((lane & 3) << 1);
                float b0 = __ldg(bqkv + col), b1 = __ldg(bqkv + col + 1);
                #pragma unroll
                for (int mt = 0; mt < 2; mt++) {
                    acc[mt][nt][0] = b0; acc[mt][nt][1] = b1;
                    acc[mt][nt][2] = b0; acc[mt][nt][3] = b1;
                }
            }
            uint32_t wb0 = wq_s + ((lane & 15) * WQ_P + c0 + ((lane >> 4) << 3)) * 2;
            #pragma unroll
            for (int kk = 0; kk < 8; kk++) {
                uint32_t b[4];
                LDSM4T(b[0], b[1], b[2], b[3], wb0 + (kk * 16 * WQ_P) * 2);
                #pragma unroll
                for (int mt = 0; mt < 2; mt++) {
                    MMA(acc[mt][0][0],acc[mt][0][1],acc[mt][0][2],acc[mt][0][3],
                        af[mt][kk][0],af[mt][kk][1],af[mt][kk][2],af[mt][kk][3],
                        b[0], b[1]);
                    MMA(acc[mt][1][0],acc[mt][1][1],acc[mt][1][2],acc[mt][1][3],
                        af[mt][kk][0],af[mt][kk][1],af[mt][kk][2],af[mt][kk][3],
                        b[2], b[3]);
                }
            }
            const float mul = (c0 < 128) ? scale : 1.0f;
            __half* dstb = (c0 < 128) ? (bufQ + c0)
                        : (c0 < 256) ? (bufK + c0 - 128)
                                     : (bufV + c0 - 256);
            #pragma unroll
            for (int mt = 0; mt < 2; mt++) {
                const int r0 = wrow + mt * 16 + (lane >> 2);
                #pragma unroll
                for (int nt = 0; nt < 2; nt++) {
                    int cl = nt * 8 + ((lane & 3) << 1);
                    if (r0 < PW)
                        *reinterpret_cast<__half2*>(dstb + r0 * BP + cl) =
                            __floats2half2_rn(acc[mt][nt][0] * mul, acc[mt][nt][1] * mul);
                    if (r0 + 8 < PW)
                        *reinterpret_cast<__half2*>(dstb + (r0 + 8) * BP + cl) =
                            __floats2half2_rn(acc[mt][nt][2] * mul, acc[mt][nt][3] * mul);
                }
            }
        }
        gbar(bid);                         // (3) qkv ready

        // ============ Phase 2: attention (2 warps per head) ============
        {
            const int h = ah;
            uint32_t kb[7][4];
            #pragma unroll
            for (int nt = 0; nt < 7; nt++) {
                uint32_t addr = k_s + ((nt * 8 + (lane & 7)) * BP
                                       + h * 32 + ((lane >> 3) << 3)) * 2;
                LDSM4(kb[nt][0], kb[nt][1], kb[nt][2], kb[nt][3], addr);
            }
            const __half* bh = g_bias + h * (49 * 56) + ((lane & 3) << 1);

            #pragma unroll
            for (int mi = 0; mi < 2; mi++) {
                const int m = amh * 2 + mi;
                uint32_t qa[4], qa2[4];
                uint32_t qaddr = q_s + ((m * 16 + (lane & 15)) * BP
                                        + h * 32 + ((lane >> 4) << 3)) * 2;
                LDSM4(qa[0], qa[1], qa[2], qa[3], qaddr);
                LDSM4(qa2[0], qa2[1], qa2[2], qa2[3], qaddr + 32);

                float s[7][4];
                #pragma unroll
                for (int nt = 0; nt < 7; nt++) {
                    s[nt][0] = s[nt][1] = s[nt][2] = s[nt][3] = 0.f;
                    MMA(s[nt][0],s[nt][1],s[nt][2],s[nt][3],
                        qa[0],qa[1],qa[2],qa[3], kb[nt][0], kb[nt][1]);
                    MMA(s[nt][0],s[nt][1],s[nt][2],s[nt][3],
                        qa2[0],qa2[1],qa2[2],qa2[3], kb[nt][2], kb[nt][3]);
                }

                // bias + mask from precomputed fp16 table (L1-resident)
                int i0 = m * 16 + (lane >> 2), i1 = i0 + 8;
                int i0c = (i0 < PW) ? i0 : 0, i1c = (i1 < PW) ? i1 : 0;
                const __half* bp0 = bh + i0c * 56;
                const __half* bp1 = bh + i1c * 56;
                #pragma unroll
                for (int nt = 0; nt < 7; nt++) {
                    float2 b0 = __half22float2(
                        __ldg(reinterpret_cast<const __half2*>(bp0 + nt * 8)));
                    float2 b1 = __half22float2(
                        __ldg(reinterpret_cast<const __half2*>(bp1 + nt * 8)));
                    s[nt][0] += b0.x; s[nt][1] += b0.y;
                    s[nt][2] += b1.x; s[nt][3] += b1.y;
                }

                float ml = -1e30f, mh2 = -1e30f;
                #pragma unroll
                for (int nt = 0; nt < 7; nt++) {
                    ml  = fmaxf(ml,  fmaxf(s[nt][0], s[nt][1]));
                    mh2 = fmaxf(mh2, fmaxf(s[nt][2], s[nt][3]));
                }
                ml  = fmaxf(ml,  __shfl_xor_sync(0xffffffffu, ml, 1));
                ml  = fmaxf(ml,  __shfl_xor_sync(0xffffffffu, ml, 2));
                mh2 = fmaxf(mh2, __shfl_xor_sync(0xffffffffu, mh2, 1));
                mh2 = fmaxf(mh2, __shfl_xor_sync(0xffffffffu, mh2, 2));
                float sl = 0.f, shs = 0.f;
                #pragma unroll
                for (int nt = 0; nt < 7; nt++) {
                    s[nt][0] = __expf(s[nt][0] - ml);  sl  += s[nt][0];
                    s[nt][1] = __expf(s[nt][1] - ml);  sl  += s[nt][1];
                    s[nt][2] = __expf(s[nt][2] - mh2); shs += s[nt][2];
                    s[nt][3] = __expf(s[nt][3] - mh2); shs += s[nt][3];
                }
                sl  += __shfl_xor_sync(0xffffffffu, sl, 1);
                sl  += __shfl_xor_sync(0xffffffffu, sl, 2);
                shs += __shfl_xor_sync(0xffffffffu, shs, 1);
                shs += __shfl_xor_sync(0xffffffffu, shs, 2);
                const float il = 1.f / sl, ih = 1.f / shs;

                uint32_t pa[4][4];
                #pragma unroll
                for (int kt = 0; kt < 4; kt++) {
                    int n0 = 2 * kt, n1 = 2 * kt + 1;
                    pa[kt][0] = f2h2(s[n0][0] * il, s[n0][1] * il);
                    pa[kt][1] = f2h2(s[n0][2] * ih, s[n0][3] * ih);
                    if (n1 < 7) {
                        pa[kt][2] = f2h2(s[n1][0] * il, s[n1][1] * il);
                        pa[kt][3] = f2h2(s[n1][2] * ih, s[n1][3] * ih);
                    } else { pa[kt][2] = 0u; pa[kt][3] = 0u; }
                }

                float o[4][4];
                #pragma unroll
                for (int d = 0; d < 4; d++) o[d][0]=o[d][1]=o[d][2]=o[d][3]=0.f;
                #pragma unroll
                for (int kt = 0; kt < 4; kt++) {
                    uint32_t vb[8];            // transient (reg-pressure cap)
                    #pragma unroll
                    for (int dp = 0; dp < 2; dp++) {
                        uint32_t addr = v_s + ((kt * 16 + (lane & 15)) * BP
                                               + h * 32 + dp * 16 + ((lane >> 4) << 3)) * 2;
                        LDSM4T(vb[dp*4+0], vb[dp*4+1], vb[dp*4+2], vb[dp*4+3], addr);
                    }
                    MMA(o[0][0],o[0][1],o[0][2],o[0][3],
                        pa[kt][0],pa[kt][1],pa[kt][2],pa[kt][3], vb[0], vb[1]);
                    MMA(o[1][0],o[1][1],o[1][2],o[1][3],
                        pa[kt][0],pa[kt][1],pa[kt][2],pa[kt][3], vb[2], vb[3]);
                    MMA(o[2][0],o[2][1],o[2][2],o[2][3],
                        pa[kt][0],pa[kt][1],pa[kt][2],pa[kt][3], vb[4], vb[5]);
                    MMA(o[3][0],o[3][1],o[3][2],o[3][3],
                        pa[kt][0],pa[kt][1],pa[kt][2],pa[kt][3], vb[6], vb[7]);
                }
                const int orow = m * 16 + (lane >> 2);
                #pragma unroll
                for (int d = 0; d < 4; d++) {
                    int col = h * 32 + d * 8 + ((lane & 3) << 1);
                    if (orow < PW)
                        *reinterpret_cast<__half2*>(bufQ + orow * BP + col) =
                            __floats2half2_rn(o[d][0], o[d][1]);
                    if (orow + 8 < PW)
                        *reinterpret_cast<__half2*>(bufQ + (orow + 8) * BP + col) =
                            __floats2half2_rn(o[d][2], o[d][3]);
                }
            }
        }
        gbar(bid);                         // (4) attn-out ready; V free

        if (win + stride < nwin) load_x(win + stride);   // overlaps phase 3

        // ============ Phase 3: out = attn_out @ Wmerge + bmerge ============
        {
            uint32_t af2[2][8][4];
            #pragma unroll
            for (int mt = 0; mt < 2; mt++) {
                uint32_t a0 = q_s + (((wrow + mt * 16) + (lane & 15)) * BP
                                     + ((lane >> 4) << 3)) * 2;
                #pragma unroll
                for (int kk = 0; kk < 8; kk++)
                    LDSM4(af2[mt][kk][0], af2[mt][kk][1], af2[mt][kk][2], af2[mt][kk][3],
                          a0 + kk * 32);
            }
            float* obase = out + (size_t)win * (PW * DD);

            #pragma unroll
            for (int nh = 0; nh < 2; nh++) {
                const int c0 = wc + nh * 16;
                float acc[2][2][4];
                #pragma unroll
                for (int nt = 0; nt < 2; nt++) {
                    int col = c0 + nt * 8 + ((lane & 3) << 1);
                    float b0 = __ldg(bmerge + col), b1 = __ldg(bmerge + col + 1);
                    #pragma unroll
                    for (int mt = 0; mt < 2; mt++) {
                        acc[mt][nt][0] = b0; acc[mt][nt][1] = b1;
                        acc[mt][nt][2] = b0; acc[mt][nt][3] = b1;
                    }
                }
                uint32_t wm0 = wm_s + ((lane & 15) * WM_P + c0 + ((lane >> 4) << 3)) * 2;
                #pragma unroll
                for (int kk = 0; kk < 8; kk++) {
                    uint32_t b[4];
                    LDSM4T(b[0], b[1], b[2], b[3], wm0 + (kk * 16 * WM_P) * 2);
                    #pragma unroll
                    for (int mt = 0; mt < 2; mt++) {
                        MMA(acc[mt][0][0],acc[mt][0][1],acc[mt][0][2],acc[mt][0][3],
                            af2[mt][kk][0],af2[mt][kk][1],af2[mt][kk][2],af2[mt][kk][3],
                            b[0], b[1]);
                        MMA(acc[mt][1][0],acc[mt][1][1],acc[mt][1][2],acc[mt][1][3],
                            af2[mt][kk][0],af2[mt][kk][1],af2[mt][kk][2],af2[mt][kk][3],
                            b[2], b[3]);
                    }
                }
                #pragma unroll
                for (int mt = 0; mt < 2; mt++) {
                    const int r0 = wrow + mt * 16 + (lane >> 2);
                    #pragma unroll
                    for (int nt = 0; nt < 2; nt++) {
                        int col = c0 + nt * 8 + ((lane & 3) << 1);
                        if (r0 < PW)
                            *reinterpret_cast<float2*>(obase + r0 * DD + col) =
                                make_float2(acc[mt][nt][0], acc[mt][nt][1]);
                        if (r0 + 8 < PW)
                            *reinterpret_cast<float2*>(obase + (r0 + 8) * DD + col) =
                                make_float2(acc[mt][nt][2], acc[mt][nt][3]);
                    }
                }
            }
        }
    }
}

extern "C" void kernel_launch(void* const* d_in, const int* in_sizes, int n_in,
                              void* d_out, int out_size)
{
    const float* x      = (const float*)d_in[0];
    const float* Wqkv   = (const float*)d_in[1];
    const float* bqkv   = (const float*)d_in[2];
    const float* Wmerge = (const float*)d_in[3];
    const float* bmerge = (const float*)d_in[4];
    const float* table  = (const float*)d_in[5];
    float* out = (float*)d_out;

    const int nwin = in_sizes[0] / (PW * DD);   // 16384

    prep_bias_kernel<<<43, 256>>>(table);

    int sms = 148;
    cudaDeviceGetAttribute(&sms, cudaDevAttrMultiProcessorCount, 0);

    cudaFuncSetAttribute(rpmha_dual3_kernel,
                         cudaFuncAttributeMaxDynamicSharedMemorySize, SMEM_BYTES);
    rpmha_dual3_kernel<<<sms, 512, SMEM_BYTES>>>(x, Wqkv, bqkv, Wmerge, bmerge,
                                                 out, nwin);
}